// round 10
// baseline (speedup 1.0000x reference)
#include <cuda_runtime.h>
#include <math.h>
#include <stdint.h>

// ContrastLoss: B=4, C=4096, K=1.
//
// lse_pairs_b   = log(sum_{lab=0} e^{pred}) + log(sum_{lab=1} e^{-pred})
// loss_contrast = (1/B) * sum_b logaddexp(lse_pairs_b, 0)
// loss_aux      = (1/B) * sum_b mean_c (aux - aux_label)^2
//
// R10 = R9 body (8-CTA cluster x 512 thr, 4 elems/thread)
//     + mbarrier tail: lane0s DSMEM-store into rank 0 smem and arrive
//       (release) on rank 0's mbarrier (count=128). Non-rank0 CTAs exit;
//       rank 0 warp 0 try_waits (acquire, ~60cyc wake vs ~490 cluster wait)
//       then reduces all 128 slots in parallel. Deterministic.

#define FULL 0xFFFFFFFFu
#define NBLK 8
#define NTHR 512
#define WPB  (NTHR / 32)            // 16 warps per CTA
#define NSLOT (NBLK * WPB)          // 128 slots, 128 mbar arrivals

__device__ __forceinline__ uint32_t smem_u32(const void* p) {
    uint32_t a;
    asm("{ .reg .u64 t; cvta.to.shared.u64 t, %1; cvt.u32.u64 %0, t; }"
        : "=r"(a) : "l"(p));
    return a;
}

__device__ __forceinline__ void acc_elem(float v, int lab, float& sn, float& sp) {
    float fl = (float)lab;
    float e  = __expf(v * fmaf(-2.f, fl, 1.f));  // exp(+v) if lab==0 else exp(-v)
    sn = fmaf(e, 1.f - fl, sn);
    sp = fmaf(e, fl, sp);
}

__global__ __launch_bounds__(NTHR, 1) __cluster_dims__(NBLK, 1, 1)
void contrast_loss_kernel(const float* __restrict__ contrast,
                          const int*   __restrict__ label,
                          const float* __restrict__ aux,
                          const float* __restrict__ aux_label,
                          float* __restrict__ out) {
    // Identical layout in every CTA; only rank 0's copy is used (mapa
    // translates local addresses to rank 0's shared memory).
    __shared__ float4   sclus[NSLOT];
    __shared__ uint64_t mbar;

    int tid = threadIdx.x;
    uint32_t rank;
    asm("mov.u32 %0, %%cluster_ctarank;" : "=r"(rank));

    // Each CTA covers 2048 contiguous elements = half of one batch.
    int base = (int)rank * 2048 + tid * 4;

    // Loads issue first; DRAM latency overlaps the mbarrier init below.
    float4 c  = *reinterpret_cast<const float4*>(contrast + base);
    int4   l  = *reinterpret_cast<const int4*>(label + base);
    float4 a  = *reinterpret_cast<const float4*>(aux + base);
    float4 al = *reinterpret_cast<const float4*>(aux_label + base);

    if (rank == 0) {
        if (tid == 0) {
            uint32_t mb = smem_u32(&mbar);
            asm volatile("mbarrier.init.shared.b64 [%0], %1;"
                         :: "r"(mb), "r"((uint32_t)NSLOT) : "memory");
            asm volatile("fence.mbarrier_init.release.cluster;" ::: "memory");
        }
        // Order rank 0's own arrivals after init. Remote CTAs' arrivals sit
        // behind a full DRAM load + reduce + DSMEM store (>=800cyc margin).
        __syncthreads();
    }

    float sn = 0.f, sp = 0.f, ax = 0.f;

    acc_elem(c.x, l.x, sn, sp);
    acc_elem(c.y, l.y, sn, sp);
    acc_elem(c.z, l.z, sn, sp);
    acc_elem(c.w, l.w, sn, sp);

    float d;
    d = a.x - al.x; ax = fmaf(d, d, ax);
    d = a.y - al.y; ax = fmaf(d, d, ax);
    d = a.z - al.z; ax = fmaf(d, d, ax);
    d = a.w - al.w; ax = fmaf(d, d, ax);

    // Warp reduction (16 warps per CTA).
    #pragma unroll
    for (int o = 16; o > 0; o >>= 1) {
        sn += __shfl_down_sync(FULL, sn, o);
        sp += __shfl_down_sync(FULL, sp, o);
        ax += __shfl_down_sync(FULL, ax, o);
    }

    // Lane 0 of each warp: store partial into rank 0's smem, then arrive
    // (release) on rank 0's mbarrier. Release orders the DSMEM store.
    if ((tid & 31) == 0) {
        int slot = (int)rank * WPB + (tid >> 5);
        uint32_t lslot = smem_u32(&sclus[slot]);
        uint32_t lmbar = smem_u32(&mbar);
        uint32_t rslot, rmbar;
        asm volatile("mapa.shared::cluster.u32 %0, %1, 0;" : "=r"(rslot) : "r"(lslot));
        asm volatile("mapa.shared::cluster.u32 %0, %1, 0;" : "=r"(rmbar) : "r"(lmbar));
        asm volatile("st.shared::cluster.v4.f32 [%0], {%1, %2, %3, %4};"
                     :: "r"(rslot), "f"(sn), "f"(sp), "f"(ax), "f"(0.f) : "memory");
        asm volatile("mbarrier.arrive.release.cluster.shared::cluster.b64 _, [%0];"
                     :: "r"(rmbar) : "memory");
    }

    // Non-rank0 CTAs are done; rank 0 warps 1..15 are done too.
    if (rank != 0 || tid >= 32) return;

    // Rank 0 warp 0: wait for all 128 arrivals (acquire, cluster scope).
    {
        uint32_t mb = smem_u32(&mbar);
        uint32_t done;
        asm volatile(
            "{\n\t"
            ".reg .pred p;\n\t"
            "WAIT_%=: \n\t"
            "mbarrier.try_wait.parity.acquire.cluster.shared::cta.b64 p, [%1], %2, 0x989680;\n\t"
            "selp.b32 %0, 1, 0, p;\n\t"
            "@!p bra.uni WAIT_%=;\n\t"
            "}"
            : "=r"(done) : "r"(mb), "r"(0u) : "memory");
    }

    // 128 slots; CTA r (batch r>>1) owns slots [16r, 16r+16) -> batch b owns
    // [32b, 32b+32). Lane l: batch = l>>3, idx = l&7; reads 4 slots.
    int b   = tid >> 3;
    int idx = tid & 7;
    float4 p0 = sclus[32 * b + idx];
    float4 p1 = sclus[32 * b + idx + 8];
    float4 p2 = sclus[32 * b + idx + 16];
    float4 p3 = sclus[32 * b + idx + 24];
    float bn = (p0.x + p1.x) + (p2.x + p3.x);
    float bp = (p0.y + p1.y) + (p2.y + p3.y);
    float ba = (p0.z + p1.z) + (p2.z + p3.z);

    // Octet butterfly: lanes within an octet share a batch.
    #pragma unroll
    for (int o = 1; o < 8; o <<= 1) {
        bn += __shfl_xor_sync(FULL, bn, o);
        bp += __shfl_xor_sync(FULL, bp, o);
        ba += __shfl_xor_sync(FULL, ba, o);
    }

    // Per-batch losses in parallel across the 4 octets.
    // Empty class -> bn or bp == 0 -> lse = -inf -> contras = 0.
    float lse     = __logf(bn) + __logf(bp);
    float contras = fmaxf(lse, 0.f) + log1pf(__expf(-fabsf(lse)));
    float laux    = ba * (1.0f / 4096.0f);

    // Keep only octet leaders, then butterfly across octets.
    if (idx != 0) { contras = 0.f; laux = 0.f; }
    contras += __shfl_xor_sync(FULL, contras, 8);
    laux    += __shfl_xor_sync(FULL, laux, 8);
    contras += __shfl_xor_sync(FULL, contras, 16);
    laux    += __shfl_xor_sync(FULL, laux, 16);

    if (tid == 0) {
        out[0] = contras * 0.25f;   // / n_items (B=4)
        out[1] = laux * 0.25f;
    }
}

extern "C" void kernel_launch(void* const* d_in, const int* in_sizes, int n_in,
                              void* d_out, int out_size) {
    const float* contrast  = (const float*)d_in[0];
    const int*   label     = (const int*)d_in[1];
    const float* aux       = (const float*)d_in[2];
    const float* aux_label = (const float*)d_in[3];
    float* out = (float*)d_out;

    contrast_loss_kernel<<<NBLK, NTHR>>>(contrast, label, aux, aux_label, out);
}